// round 16
// baseline (speedup 1.0000x reference)
#include <cuda_runtime.h>

// Problem constants
constexpr int KT   = 8192;   // timesteps
constexpr int KH   = 1024;   // hidden size
constexpr int NBLK = 128;    // persistent blocks (<= 148/152 SMs -> all co-resident wave 1)
constexpr int TPB  = 256;    // threads per block (8 warps)
constexpr int UPB  = 8;      // hidden units per block (1 per warp)

// h broadcast buffer: slot s holds h_{s-1} (input to step s), KH floats per slot.
// Values are PLAIN data; validity is signaled solely by g_cnt (release/acquire).
__device__ float    g_h[(size_t)(KT + 1) * KH];
// g_cnt[s] == NBLK  <=>  slot s fully published. Strong ops only.
__device__ unsigned g_cnt[KT + 1];
// Per-(step, block) partial of W_fc . h
__device__ float    g_partial[(size_t)KT * NBLK];

// ---------------- helpers ----------------
__device__ __forceinline__ unsigned long long fma2(unsigned long long a,
                                                   unsigned long long b,
                                                   unsigned long long c) {
    unsigned long long d;
    asm("fma.rn.f32x2 %0, %1, %2, %3;" : "=l"(d) : "l"(a), "l"(b), "l"(c));
    return d;
}
__device__ __forceinline__ unsigned long long pack2(float lo, float hi) {
    unsigned long long r;
    asm("mov.b64 %0, {%1,%2};" : "=l"(r) : "f"(lo), "f"(hi));
    return r;
}
__device__ __forceinline__ void unpack2(unsigned long long v, float& lo, float& hi) {
    asm("mov.b64 {%0,%1}, %2;" : "=f"(lo), "=f"(hi) : "l"(v));
}
__device__ __forceinline__ unsigned ld_acq(const unsigned* p) {
    unsigned v;
    asm volatile("ld.acquire.gpu.global.u32 %0, [%1];" : "=r"(v) : "l"(p) : "memory");
    return v;
}
__device__ __forceinline__ void red_rel_add(unsigned* p, unsigned v) {
    asm volatile("red.release.gpu.global.add.u32 [%0], %1;" ::"l"(p), "r"(v) : "memory");
}
__device__ __forceinline__ float sigmoidf_(float x) {
    return __fdividef(1.f, 1.f + __expf(-x));
}
__device__ __forceinline__ float tanhf_(float x) {
    // sign-safe: e in (0,1], no inf/inf
    float e = __expf(-2.f * fabsf(x));
    float r = __fdividef(1.f - e, 1.f + e);
    return copysignf(r, x);
}

// ---------------- init: reset counters each replay (runs inside the graph) ----------------
__global__ void init_kernel() {
    int i = blockIdx.x * blockDim.x + threadIdx.x;
    if (i <= KT) g_cnt[i] = (i == 0) ? (unsigned)NBLK : 0u;  // slot 0 pre-valid
    if (i < KH)  g_h[i] = 0.f;                               // h0 = 0
}

// ---------------- persistent LSTM ----------------
__global__ void __launch_bounds__(TPB, 1) lstm_kernel(
    const float* __restrict__ x, const float* __restrict__ W_ih,
    const float* __restrict__ W_hh, const float* __restrict__ b_ih,
    const float* __restrict__ b_hh, const float* __restrict__ W_fc) {
    // Double-buffered h (f32x2 pairs), parity = s & 1 (belt-and-suspenders; with
    // the two barriers per step single-buffering would also be safe).
    __shared__ unsigned long long h_sm[2][KH / 2];
    __shared__ float s_part[2][UPB];   // W_fc partials, parity-buffered
    __shared__ float s_hval[2][UPB];   // this block's h values for tid0 to publish

    const int tid = threadIdx.x;
    const int w   = tid >> 5;
    const int l   = tid & 31;
    const int u   = blockIdx.x * UPB + w;  // hidden unit owned by this warp

    // Register-resident W_hh slice.
    // Lane l owns f32x2 pairs p = l + 32*j (j=0..15) of each of 4 gate rows
    // (strided so LDS of h pairs is conflict-free and GMEM loads coalesce).
    unsigned long long wreg[4][16];
#pragma unroll
    for (int g = 0; g < 4; ++g) {
        const unsigned long long* rp =
            reinterpret_cast<const unsigned long long*>(W_hh + (size_t)(g * KH + u) * KH);
#pragma unroll
        for (int j = 0; j < 16; ++j) wreg[g][j] = __ldg(rp + l + 32 * j);
    }
    float wih[4], bsum[4];
#pragma unroll
    for (int g = 0; g < 4; ++g) {
        wih[g]  = __ldg(W_ih + g * KH + u);
        bsum[g] = __ldg(b_ih + g * KH + u) + __ldg(b_hh + g * KH + u);
    }
    const float wfc = __ldg(W_fc + u);

    float c = 0.f;  // cell state (replicated across the warp's lanes)

    for (int s = 0; s < KT; ++s) {
        const int   p  = s & 1;
        const float xt = __ldg(x + s);

        // ---- acquire-poll: slot s valid once g_cnt[s] == NBLK ----
        // Each thread's own acquire load synchronizes-with the release-RMW chain,
        // so its subsequent plain loads of slot s observe all producers' stores.
        while (ld_acq(&g_cnt[s]) != (unsigned)NBLK) {}

        // ---- stage h_{s-1}: thread stages units 4*tid .. 4*tid+3 (plain v4 ld) ----
        float4 v = *(reinterpret_cast<const float4*>(g_h + (size_t)s * KH) + tid);
        h_sm[p][2 * tid]     = pack2(v.x, v.y);
        h_sm[p][2 * tid + 1] = pack2(v.z, v.w);
        __syncthreads();  // (#1) staging complete before any read of buffer p

        // flush previous step's fc-partials (off critical path)
        if (tid == 0 && s > 0) {
            float q = 0.f;
#pragma unroll
            for (int k = 0; k < UPB; ++k) q += s_part[p ^ 1][k];
            g_partial[(size_t)(s - 1) * NBLK + blockIdx.x] = q;
        }

        // ---- matvec: 4 gate rows, packed f32x2 FMAs ----
        unsigned long long a0 = 0ull, a1 = 0ull, a2 = 0ull, a3 = 0ull;
#pragma unroll
        for (int j = 0; j < 16; ++j) {
            unsigned long long hv = h_sm[p][l + 32 * j];
            a0 = fma2(wreg[0][j], hv, a0);
            a1 = fma2(wreg[1][j], hv, a1);
            a2 = fma2(wreg[2][j], hv, a2);
            a3 = fma2(wreg[3][j], hv, a3);
        }
        float s0, s1, s2, s3, lo, hi;
        unpack2(a0, lo, hi); s0 = lo + hi;
        unpack2(a1, lo, hi); s1 = lo + hi;
        unpack2(a2, lo, hi); s2 = lo + hi;
        unpack2(a3, lo, hi); s3 = lo + hi;
#pragma unroll
        for (int off = 16; off; off >>= 1) {
            s0 += __shfl_xor_sync(0xffffffffu, s0, off);
            s1 += __shfl_xor_sync(0xffffffffu, s1, off);
            s2 += __shfl_xor_sync(0xffffffffu, s2, off);
            s3 += __shfl_xor_sync(0xffffffffu, s3, off);
        }

        // ---- pointwise gates (all lanes redundantly -> identical values) ----
        float gi = sigmoidf_(s0 + xt * wih[0] + bsum[0]);
        float gf = sigmoidf_(s1 + xt * wih[1] + bsum[1]);
        float gg = tanhf_(s2 + xt * wih[2] + bsum[2]);
        float go = sigmoidf_(s3 + xt * wih[3] + bsum[3]);
        c        = gf * c + gi * gg;
        float hn = go * tanhf_(c);

        if (l == 0) {
            s_hval[p][w] = hn;
            s_part[p][w] = wfc * hn;
        }
        __syncthreads();  // (#2) all 8 h values in s_hval before tid0 publishes

        // ---- publish: tid0 stores the block's 8 h values, then release-add ----
        // tid0's plain stores are program-ordered before its release RMW, so any
        // consumer whose acquire poll observes the count sees these stores.
        if (tid == 0) {
            float* dst = g_h + (size_t)(s + 1) * KH + blockIdx.x * UPB;
            float4 h0  = make_float4(s_hval[p][0], s_hval[p][1], s_hval[p][2], s_hval[p][3]);
            float4 h1  = make_float4(s_hval[p][4], s_hval[p][5], s_hval[p][6], s_hval[p][7]);
            *reinterpret_cast<float4*>(dst)     = h0;
            *reinterpret_cast<float4*>(dst + 4) = h1;
            red_rel_add(&g_cnt[s + 1], 1u);
        }
    }
    if (tid == 0) {
        float q = 0.f;
#pragma unroll
        for (int k = 0; k < UPB; ++k) q += s_part[(KT - 1) & 1][k];
        g_partial[(size_t)(KT - 1) * NBLK + blockIdx.x] = q;
    }
}

// ---------------- deterministic epilogue: out[t] = sum_j partial[t][j] + b_fc ----------------
__global__ void finalize_kernel(const float* __restrict__ b_fc, float* __restrict__ out) {
    int warp = (blockIdx.x * blockDim.x + threadIdx.x) >> 5;
    int l    = threadIdx.x & 31;
    if (warp >= KT) return;
    const float* p = g_partial + (size_t)warp * NBLK;
    float s = p[l] + p[l + 32] + p[l + 64] + p[l + 96];
#pragma unroll
    for (int off = 16; off; off >>= 1) s += __shfl_xor_sync(0xffffffffu, s, off);
    if (l == 0) out[warp] = s + __ldg(b_fc);
}

extern "C" void kernel_launch(void* const* d_in, const int* in_sizes, int n_in,
                              void* d_out, int out_size) {
    const float* x    = (const float*)d_in[0];
    const float* W_ih = (const float*)d_in[1];
    const float* W_hh = (const float*)d_in[2];
    const float* b_ih = (const float*)d_in[3];
    const float* b_hh = (const float*)d_in[4];
    const float* W_fc = (const float*)d_in[5];
    const float* b_fc = (const float*)d_in[6];

    init_kernel<<<(KT + 1 + 255) / 256, 256>>>();
    lstm_kernel<<<NBLK, TPB>>>(x, W_ih, W_hh, b_ih, b_hh, W_fc);
    finalize_kernel<<<(KT * 32) / TPB, TPB>>>(b_fc, (float*)d_out);
}

// round 17
// speedup vs baseline: 1.4443x; 1.4443x over previous
#include <cuda_runtime.h>

// Problem constants
constexpr int KT   = 8192;   // timesteps
constexpr int KH   = 1024;   // hidden size
constexpr int NBLK = 128;    // persistent blocks (<= 148/152 SMs -> all co-resident wave 1)
constexpr int TPB  = 256;    // threads per block (8 warps)
constexpr int UPB  = 8;      // hidden units per block (1 per warp)

// h broadcast buffer: slot s holds h_{s-1} (input to step s), KH floats per slot.
// Values are PLAIN data; validity is signaled solely by g_cnt (release/acquire).
__device__ float    g_h[(size_t)(KT + 1) * KH];
// g_cnt[s] == NBLK  <=>  slot s fully published. Strong ops only.
__device__ unsigned g_cnt[KT + 1];
// Per-(step, block) partial of W_fc . h
__device__ float    g_partial[(size_t)KT * NBLK];

// ---------------- helpers ----------------
__device__ __forceinline__ unsigned long long fma2(unsigned long long a,
                                                   unsigned long long b,
                                                   unsigned long long c) {
    unsigned long long d;
    asm("fma.rn.f32x2 %0, %1, %2, %3;" : "=l"(d) : "l"(a), "l"(b), "l"(c));
    return d;
}
__device__ __forceinline__ unsigned long long pack2(float lo, float hi) {
    unsigned long long r;
    asm("mov.b64 %0, {%1,%2};" : "=l"(r) : "f"(lo), "f"(hi));
    return r;
}
__device__ __forceinline__ void unpack2(unsigned long long v, float& lo, float& hi) {
    asm("mov.b64 {%0,%1}, %2;" : "=f"(lo), "=f"(hi) : "l"(v));
}
__device__ __forceinline__ unsigned ld_acq(const unsigned* p) {
    unsigned v;
    asm volatile("ld.acquire.gpu.global.u32 %0, [%1];" : "=r"(v) : "l"(p) : "memory");
    return v;
}
__device__ __forceinline__ void red_rel_add(unsigned* p, unsigned v) {
    asm volatile("red.release.gpu.global.add.u32 [%0], %1;" ::"l"(p), "r"(v) : "memory");
}
__device__ __forceinline__ void stg1(float* p, float v) {
    asm volatile("st.global.f32 [%0], %1;" ::"l"(p), "f"(v) : "memory");
}
__device__ __forceinline__ float sigmoidf_(float x) {
    return __fdividef(1.f, 1.f + __expf(-x));
}
__device__ __forceinline__ float tanhf_(float x) {
    // sign-safe: e in (0,1], no inf/inf
    float e = __expf(-2.f * fabsf(x));
    float r = __fdividef(1.f - e, 1.f + e);
    return copysignf(r, x);
}

// ---------------- init: reset counters each replay (runs inside the graph) ----------------
__global__ void init_kernel() {
    int i = blockIdx.x * blockDim.x + threadIdx.x;
    if (i <= KT) g_cnt[i] = (i == 0) ? (unsigned)NBLK : 0u;  // slot 0 pre-valid
    if (i < KH)  g_h[i] = 0.f;                               // h0 = 0
}

// ---------------- persistent LSTM ----------------
__global__ void __launch_bounds__(TPB, 1) lstm_kernel(
    const float* __restrict__ x, const float* __restrict__ W_ih,
    const float* __restrict__ W_hh, const float* __restrict__ b_ih,
    const float* __restrict__ b_hh, const float* __restrict__ W_fc) {
    // Double-buffered h (f32x2 pairs), parity = s & 1.
    __shared__ unsigned long long h_sm[2][KH / 2];
    __shared__ float s_part[2][UPB];   // W_fc partials, parity-buffered

    const int tid = threadIdx.x;
    const int w   = tid >> 5;
    const int l   = tid & 31;
    const int u   = blockIdx.x * UPB + w;  // hidden unit owned by this warp

    // Register-resident W_hh slice.
    // Lane l owns f32x2 pairs p = l + 32*j (j=0..15) of each of 4 gate rows
    // (strided so LDS of h pairs is conflict-free and GMEM loads coalesce).
    unsigned long long wreg[4][16];
#pragma unroll
    for (int g = 0; g < 4; ++g) {
        const unsigned long long* rp =
            reinterpret_cast<const unsigned long long*>(W_hh + (size_t)(g * KH + u) * KH);
#pragma unroll
        for (int j = 0; j < 16; ++j) wreg[g][j] = __ldg(rp + l + 32 * j);
    }
    float wih[4], bsum[4];
#pragma unroll
    for (int g = 0; g < 4; ++g) {
        wih[g]  = __ldg(W_ih + g * KH + u);
        bsum[g] = __ldg(b_ih + g * KH + u) + __ldg(b_hh + g * KH + u);
    }
    const float wfc = __ldg(W_fc + u);

    float c = 0.f;  // cell state (replicated across the warp's lanes)

    for (int s = 0; s < KT; ++s) {
        const int   p  = s & 1;
        const float xt = __ldg(x + s);

        // ---- acquire-poll by tid0 ONLY (contention fix): slot s valid once
        // g_cnt[s] == NBLK. tid0's acquire synchronizes-with the release-RMW
        // chain; barrier (#1) below extends visibility to the whole CTA
        // (cumulativity). 128 pollers chip-wide instead of 32768.
        if (tid == 0) {
            while (ld_acq(&g_cnt[s]) != (unsigned)NBLK) {}
        }
        __syncthreads();  // (#1a) release of poll result to all threads

        // ---- stage h_{s-1}: thread stages units 4*tid .. 4*tid+3 (plain v4 ld;
        // lines are first-touch for this SM at this step -> no L1 staleness) ----
        float4 v = *(reinterpret_cast<const float4*>(g_h + (size_t)s * KH) + tid);
        h_sm[p][2 * tid]     = pack2(v.x, v.y);
        h_sm[p][2 * tid + 1] = pack2(v.z, v.w);
        __syncthreads();  // (#1b) staging complete before any read of buffer p

        // flush previous step's fc-partials (off critical path; warp 1 lane 0,
        // keeping tid0 = poller lean)
        if (tid == 32 && s > 0) {
            float q = 0.f;
#pragma unroll
            for (int k = 0; k < UPB; ++k) q += s_part[p ^ 1][k];
            g_partial[(size_t)(s - 1) * NBLK + blockIdx.x] = q;
        }

        // ---- matvec: 4 gate rows, packed f32x2 FMAs ----
        unsigned long long a0 = 0ull, a1 = 0ull, a2 = 0ull, a3 = 0ull;
#pragma unroll
        for (int j = 0; j < 16; ++j) {
            unsigned long long hv = h_sm[p][l + 32 * j];
            a0 = fma2(wreg[0][j], hv, a0);
            a1 = fma2(wreg[1][j], hv, a1);
            a2 = fma2(wreg[2][j], hv, a2);
            a3 = fma2(wreg[3][j], hv, a3);
        }
        float s0, s1, s2, s3, lo, hi;
        unpack2(a0, lo, hi); s0 = lo + hi;
        unpack2(a1, lo, hi); s1 = lo + hi;
        unpack2(a2, lo, hi); s2 = lo + hi;
        unpack2(a3, lo, hi); s3 = lo + hi;
#pragma unroll
        for (int off = 16; off; off >>= 1) {
            s0 += __shfl_xor_sync(0xffffffffu, s0, off);
            s1 += __shfl_xor_sync(0xffffffffu, s1, off);
            s2 += __shfl_xor_sync(0xffffffffu, s2, off);
            s3 += __shfl_xor_sync(0xffffffffu, s3, off);
        }

        // ---- pointwise gates (all lanes redundantly -> identical values) ----
        float gi = sigmoidf_(s0 + xt * wih[0] + bsum[0]);
        float gf = sigmoidf_(s1 + xt * wih[1] + bsum[1]);
        float gg = tanhf_(s2 + xt * wih[2] + bsum[2]);
        float go = sigmoidf_(s3 + xt * wih[3] + bsum[3]);
        c        = gf * c + gi * gg;
        float hn = go * tanhf_(c);

        // ---- publish: each warp's lane0 stores its h the moment it's ready
        // (overlaps slower sibling warps), then one release-add after the
        // barrier orders all 8 stores (A-cumulativity of the release RMW).
        if (l == 0) {
            stg1(&g_h[(size_t)(s + 1) * KH + u], hn);
            s_part[p][w] = wfc * hn;
        }
        __syncthreads();  // (#2) all 8 h stores issued before the release-add
        if (tid == 0) red_rel_add(&g_cnt[s + 1], 1u);
    }
    if (tid == 32) {
        float q = 0.f;
#pragma unroll
        for (int k = 0; k < UPB; ++k) q += s_part[(KT - 1) & 1][k];
        g_partial[(size_t)(KT - 1) * NBLK + blockIdx.x] = q;
    }
}

// ---------------- deterministic epilogue: out[t] = sum_j partial[t][j] + b_fc ----------------
__global__ void finalize_kernel(const float* __restrict__ b_fc, float* __restrict__ out) {
    int warp = (blockIdx.x * blockDim.x + threadIdx.x) >> 5;
    int l    = threadIdx.x & 31;
    if (warp >= KT) return;
    const float* p = g_partial + (size_t)warp * NBLK;
    float s = p[l] + p[l + 32] + p[l + 64] + p[l + 96];
#pragma unroll
    for (int off = 16; off; off >>= 1) s += __shfl_xor_sync(0xffffffffu, s, off);
    if (l == 0) out[warp] = s + __ldg(b_fc);
}

extern "C" void kernel_launch(void* const* d_in, const int* in_sizes, int n_in,
                              void* d_out, int out_size) {
    const float* x    = (const float*)d_in[0];
    const float* W_ih = (const float*)d_in[1];
    const float* W_hh = (const float*)d_in[2];
    const float* b_ih = (const float*)d_in[3];
    const float* b_hh = (const float*)d_in[4];
    const float* W_fc = (const float*)d_in[5];
    const float* b_fc = (const float*)d_in[6];

    init_kernel<<<(KT + 1 + 255) / 256, 256>>>();
    lstm_kernel<<<NBLK, TPB>>>(x, W_ih, W_hh, b_ih, b_hh, W_fc);
    finalize_kernel<<<(KT * 32) / TPB, TPB>>>(b_fc, (float*)d_out);
}